// round 12
// baseline (speedup 1.0000x reference)
#include <cuda_runtime.h>
#include <cuda_bf16.h>
#include <stdint.h>
#include <math.h>

#define N_ROWS 65536
#define DIM    256
#define KCODES 1024
#define BM     128
#define NBLOCKS (N_ROWS / BM)   // 512
#define NCHUNK  8               // codes: 8 chunks of 128
#define NPANEL  4               // K: 4 panels of 64
#define NIDX    (NCHUNK * NPANEL)
#define POS_INF __builtin_huge_valf()
#define FLAG_EPS 8e-5f

// ---------------- device globals ----------------
__device__ float g_norm_e[KCODES];
__device__ float g_norm_x[N_ROWS];
__device__ float g_partial[NBLOCKS];
__device__ int   g_idx[N_ROWS];
__device__ int   g_flaglist[N_ROWS];
__device__ int   g_nflag;
// codebook bf16 limbs, row-major [1024][256]
__device__ __align__(16) __nv_bfloat16 g_eh[KCODES * DIM];
__device__ __align__(16) __nv_bfloat16 g_el[KCODES * DIM];

// ---------------- smem layout (main kernel) ----------------
#define XPITCH 528     // [128 rows][264 bf16] pad -> ldmatrix conflict-free
#define EPITCH 144     // [128 codes][72 bf16]
#define ETILE  (128 * EPITCH)       // 18432 (one limb, one stage)
#define ESTAGE (2 * ETILE)          // 36864 (EH + EL, one stage)
#define OFF_XH  0                   // 67584
#define OFF_XL  67584               // 67584 (end 135168)
#define OFF_E   135168              // 2 stages x (EH,EL) = 73728 (end 208896)
#define OFF_NE  208896              // 4096
#define OFF_NX  212992              // 512
#define OFF_MV1 213504              // float [2][128]  (min1 per col-half)
#define OFF_MV2 214528              // float [2][128]  (min2)
#define OFF_MID 215552              // int   [2][128]  (idx)
#define SMEM_BYTES 216576

__device__ __forceinline__ uint32_t smem_u32(const void* p) {
    uint32_t a;
    asm("{ .reg .u64 t; cvta.to.shared.u64 t, %1; cvt.u32.u64 %0, t; }" : "=r"(a) : "l"(p));
    return a;
}
__device__ __forceinline__ void ldm_x4(uint32_t& r0, uint32_t& r1, uint32_t& r2, uint32_t& r3,
                                       uint32_t addr) {
    asm volatile("ldmatrix.sync.aligned.m8n8.x4.shared.b16 {%0,%1,%2,%3}, [%4];"
                 : "=r"(r0), "=r"(r1), "=r"(r2), "=r"(r3) : "r"(addr));
}
__device__ __forceinline__ void mma16816(float* c, uint32_t a0, uint32_t a1, uint32_t a2,
                                         uint32_t a3, uint32_t b0, uint32_t b1) {
    asm volatile("mma.sync.aligned.m16n8k16.row.col.f32.bf16.bf16.f32 "
                 "{%0,%1,%2,%3}, {%4,%5,%6,%7}, {%8,%9}, {%0,%1,%2,%3};"
                 : "+f"(c[0]), "+f"(c[1]), "+f"(c[2]), "+f"(c[3])
                 : "r"(a0), "r"(a1), "r"(a2), "r"(a3), "r"(b0), "r"(b1));
}
__device__ __forceinline__ void cp_async16(uint32_t dst, const void* src) {
    size_t g = __cvta_generic_to_global(src);
    asm volatile("cp.async.cg.shared.global [%0], [%1], 16;" :: "r"(dst), "l"(g) : "memory");
}
#define CP_COMMIT() asm volatile("cp.async.commit_group;" ::: "memory")
template <int N>
__device__ __forceinline__ void cp_wait() {
    asm volatile("cp.async.wait_group %0;" :: "n"(N) : "memory");
}
__device__ __forceinline__ uint32_t pack2(__nv_bfloat16 a, __nv_bfloat16 b) {
    __nv_bfloat162 p = __halves2bfloat162(a, b);
    return reinterpret_cast<uint32_t&>(p);
}
__device__ __forceinline__ void split2(float x, __nv_bfloat16& h, __nv_bfloat16& l) {
    h = __float2bfloat16(x);
    l = __float2bfloat16(__fsub_rn(x, __bfloat162float(h)));
}

// ---------------------------------------------------------------------------
// Kernel 1a: ||e_k||^2 + flag-counter reset
// ---------------------------------------------------------------------------
__global__ void vq_norms_e_kernel(const float* __restrict__ emb) {
    if (blockIdx.x == 0 && threadIdx.x == 0) g_nflag = 0;
    int k = blockIdx.x * blockDim.x + threadIdx.x;
    if (k < KCODES) {
        const float4* e4 = (const float4*)(emb + (size_t)k * DIM);
        float s = 0.0f;
        #pragma unroll 8
        for (int q = 0; q < DIM / 4; q++) {
            float4 v = e4[q];
            s += v.x * v.x + v.y * v.y + v.z * v.z + v.w * v.w;
        }
        g_norm_e[k] = s;
    }
}
// ---------------------------------------------------------------------------
// Kernel 1b: ||x_r||^2  (bit-identical to passing version)
// ---------------------------------------------------------------------------
__global__ void vq_norms_x_kernel(const float* __restrict__ lat) {
    int warp = (blockIdx.x * blockDim.x + threadIdx.x) >> 5;
    int lane = threadIdx.x & 31;
    if (warp < N_ROWS) {
        const float4* x4 = (const float4*)(lat + (size_t)warp * DIM);
        float s = 0.0f;
        #pragma unroll
        for (int q = 0; q < 2; q++) {
            float4 v = x4[lane + 32 * q];
            s += v.x * v.x + v.y * v.y + v.z * v.z + v.w * v.w;
        }
        #pragma unroll
        for (int off = 16; off >= 1; off >>= 1)
            s += __shfl_xor_sync(0xffffffffu, s, off);
        if (lane == 0) g_norm_x[warp] = s;
    }
}
// ---------------------------------------------------------------------------
// Kernel 1c: codebook -> bf16 limbs, row-major
// ---------------------------------------------------------------------------
__global__ void vq_convert_e_kernel(const float* __restrict__ emb) {
    int t = blockIdx.x * blockDim.x + threadIdx.x;   // 65536
    int k  = t >> 6;
    int c4 = t & 63;
    float4 v = ((const float4*)emb)[(size_t)k * 64 + c4];
    __nv_bfloat16 h0, h1, h2, h3, l0, l1, l2, l3;
    split2(v.x, h0, l0); split2(v.y, h1, l1);
    split2(v.z, h2, l2); split2(v.w, h3, l3);
    uint2 uh; uh.x = pack2(h0, h1); uh.y = pack2(h2, h3);
    uint2 ul; ul.x = pack2(l0, l1); ul.y = pack2(l2, l3);
    *(uint2*)((char*)g_eh + (size_t)k * 512 + c4 * 8) = uh;
    *(uint2*)((char*)g_el + (size_t)k * 512 + c4 * 8) = ul;
}

// ---------------------------------------------------------------------------
// Kernel 2: mma.sync split-bf16 GEMM (32x64 warp tiles, cp.async pipelined)
//           + argmin(min1,min2) + ambiguity flag
// ---------------------------------------------------------------------------
__global__ void __launch_bounds__(256, 1)
vq_main_kernel(const float* __restrict__ lat) {
    extern __shared__ char sm[];
    const uint32_t sb = smem_u32(sm);

    const int tid  = threadIdx.x;
    const int wid  = tid >> 5;
    const int lane = tid & 31;
    const int g    = lane >> 2;
    const int tig  = lane & 3;
    const int rg   = wid & 3;        // row group: rows [32*rg, 32*rg+32)
    const int ch   = wid >> 2;       // col half:  cols [64*ch, 64*ch+64)
    const int r0   = blockIdx.x * BM;

    float* sNE = (float*)(sm + OFF_NE);
    float* sNX = (float*)(sm + OFF_NX);

    // ---- prologue: issue first E panel immediately ----
    {
        const char* srcH = (const char*)g_eh;           // cc=0, p=0
        const char* srcL = (const char*)g_el;
        #pragma unroll
        for (int t = tid; t < 1024; t += 256) {
            int r = t >> 3, c16 = t & 7;
            cp_async16(sb + OFF_E + r * EPITCH + c16 * 16, srcH + (size_t)r * 512 + c16 * 16);
            cp_async16(sb + OFF_E + ETILE + r * EPITCH + c16 * 16, srcL + (size_t)r * 512 + c16 * 16);
        }
        CP_COMMIT();
    }

    for (int t = tid; t < KCODES; t += 256) sNE[t] = g_norm_e[t];
    if (tid < BM) sNX[tid] = g_norm_x[r0 + tid];

    // build x limb tiles (x read once for the GEMM)
    const float4* lat4 = (const float4*)lat;
    for (int t = tid; t < BM * 64; t += 256) {
        int row = t >> 6, c4 = t & 63;
        float4 v = lat4[(size_t)(r0 + row) * 64 + c4];
        __nv_bfloat16 h0, h1, h2, h3, l0, l1, l2, l3;
        split2(v.x, h0, l0); split2(v.y, h1, l1);
        split2(v.z, h2, l2); split2(v.w, h3, l3);
        uint2 uh; uh.x = pack2(h0, h1); uh.y = pack2(h2, h3);
        uint2 ul; ul.x = pack2(l0, l1); ul.y = pack2(l2, l3);
        *(uint2*)(sm + OFF_XH + row * XPITCH + c4 * 8) = uh;
        *(uint2*)(sm + OFF_XL + row * XPITCH + c4 * 8) = ul;
    }
    __syncthreads();

    // ldmatrix lane addressing
    const uint32_t a_off0 = (uint32_t)(32 * rg + (lane & 15)) * XPITCH + (lane >> 4) * 16;
    const uint32_t a_off1 = a_off0 + 16 * XPITCH;
    const uint32_t b_lane = (uint32_t)((lane & 7) + ((lane >> 4) & 1) * 8) * EPITCH
                          + ((lane >> 3) & 1) * 16
                          + (uint32_t)(64 * ch) * EPITCH;

    const float nx00 = sNX[32 * rg + g];           // m=0 lo
    const float nx01 = sNX[32 * rg + g + 8];       // m=0 hi
    const float nx10 = sNX[32 * rg + 16 + g];      // m=1 lo
    const float nx11 = sNX[32 * rg + 16 + g + 8];  // m=1 hi

    float bv[2][2], b2[2][2];
    int   bi[2][2];
    #pragma unroll
    for (int m = 0; m < 2; m++)
        #pragma unroll
        for (int lh = 0; lh < 2; lh++) {
            bv[m][lh] = POS_INF; b2[m][lh] = POS_INF; bi[m][lh] = 0;
        }

    float acc[2][8][4];

    for (int idx = 0; idx < NIDX; idx++) {
        const int cc  = idx >> 2;
        const int p   = idx & 3;
        const int cur = idx & 1;

        // issue next panel into alternate stage, then wait for current
        if (idx + 1 < NIDX) {
            const int ncc = (idx + 1) >> 2, np2 = (idx + 1) & 3, nst = (idx + 1) & 1;
            const char* srcH = (const char*)g_eh + ((size_t)ncc * 128) * 512 + np2 * 128;
            const char* srcL = (const char*)g_el + ((size_t)ncc * 128) * 512 + np2 * 128;
            const uint32_t dH = sb + OFF_E + nst * ESTAGE;
            const uint32_t dL = dH + ETILE;
            #pragma unroll
            for (int t = tid; t < 1024; t += 256) {
                int r = t >> 3, c16 = t & 7;
                cp_async16(dH + r * EPITCH + c16 * 16, srcH + (size_t)r * 512 + c16 * 16);
                cp_async16(dL + r * EPITCH + c16 * 16, srcL + (size_t)r * 512 + c16 * 16);
            }
            CP_COMMIT();
            cp_wait<1>();
        } else {
            cp_wait<0>();
        }
        __syncthreads();

        if (p == 0) {
            #pragma unroll
            for (int m = 0; m < 2; m++)
                #pragma unroll
                for (int j = 0; j < 8; j++)
                    #pragma unroll
                    for (int q = 0; q < 4; q++) acc[m][j][q] = 0.0f;
        }

        const uint32_t bh_base = sb + OFF_E + cur * ESTAGE + b_lane;
        const uint32_t bl_base = bh_base + ETILE;

        #pragma unroll
        for (int kk = 0; kk < 4; kk++) {
            const int ks = p * 4 + kk;
            uint32_t ah[2][4], al[2][4];
            ldm_x4(ah[0][0], ah[0][1], ah[0][2], ah[0][3], sb + OFF_XH + a_off0 + ks * 32);
            ldm_x4(al[0][0], al[0][1], al[0][2], al[0][3], sb + OFF_XL + a_off0 + ks * 32);
            ldm_x4(ah[1][0], ah[1][1], ah[1][2], ah[1][3], sb + OFF_XH + a_off1 + ks * 32);
            ldm_x4(al[1][0], al[1][1], al[1][2], al[1][3], sb + OFF_XL + a_off1 + ks * 32);
            #pragma unroll
            for (int nt = 0; nt < 4; nt++) {
                uint32_t bh0, bh1, bh2, bh3, bl0, bl1, bl2, bl3;
                ldm_x4(bh0, bh1, bh2, bh3, bh_base + nt * (16 * EPITCH) + kk * 32);
                ldm_x4(bl0, bl1, bl2, bl3, bl_base + nt * (16 * EPITCH) + kk * 32);
                #pragma unroll
                for (int m = 0; m < 2; m++) {
                    // order per (row,col): hh, lh, hl  (identical to R11)
                    mma16816(acc[m][2 * nt],     ah[m][0], ah[m][1], ah[m][2], ah[m][3], bh0, bh1);
                    mma16816(acc[m][2 * nt],     al[m][0], al[m][1], al[m][2], al[m][3], bh0, bh1);
                    mma16816(acc[m][2 * nt],     ah[m][0], ah[m][1], ah[m][2], ah[m][3], bl0, bl1);
                    mma16816(acc[m][2 * nt + 1], ah[m][0], ah[m][1], ah[m][2], ah[m][3], bh2, bh3);
                    mma16816(acc[m][2 * nt + 1], al[m][0], al[m][1], al[m][2], al[m][3], bh2, bh3);
                    mma16816(acc[m][2 * nt + 1], ah[m][0], ah[m][1], ah[m][2], ah[m][3], bl2, bl3);
                }
            }
        }
        __syncthreads();   // all warps done with stage `cur` before it is refilled

        // ---- per-chunk argmin fold (after panel 3) ----
        if (p == 3) {
            const float* nep = sNE + cc * 128;
            #pragma unroll
            for (int j = 0; j < 8; j++) {
                const int nt = j >> 1, h = j & 1;
                const int nc = 64 * ch + nt * 16 + 8 * h + 2 * tig;
                const int col0 = cc * 128 + nc;
                const float ne0 = nep[nc], ne1 = nep[nc + 1];
                float s;
                #pragma unroll
                for (int m = 0; m < 2; m++) {
                    const float nxl = (m == 0) ? nx00 : nx10;
                    const float nxh = (m == 0) ? nx01 : nx11;
                    s = __fsub_rn(__fadd_rn(nxl, ne0), __fmul_rn(2.0f, acc[m][j][0]));
                    if (s < bv[m][0]) { b2[m][0] = bv[m][0]; bv[m][0] = s; bi[m][0] = col0; }
                    else if (s < b2[m][0]) b2[m][0] = s;
                    s = __fsub_rn(__fadd_rn(nxl, ne1), __fmul_rn(2.0f, acc[m][j][1]));
                    if (s < bv[m][0]) { b2[m][0] = bv[m][0]; bv[m][0] = s; bi[m][0] = col0 + 1; }
                    else if (s < b2[m][0]) b2[m][0] = s;
                    s = __fsub_rn(__fadd_rn(nxh, ne0), __fmul_rn(2.0f, acc[m][j][2]));
                    if (s < bv[m][1]) { b2[m][1] = bv[m][1]; bv[m][1] = s; bi[m][1] = col0; }
                    else if (s < b2[m][1]) b2[m][1] = s;
                    s = __fsub_rn(__fadd_rn(nxh, ne1), __fmul_rn(2.0f, acc[m][j][3]));
                    if (s < bv[m][1]) { b2[m][1] = bv[m][1]; bv[m][1] = s; bi[m][1] = col0 + 1; }
                    else if (s < b2[m][1]) b2[m][1] = s;
                }
            }
        }
    }

    // ---- quad reduce (lex (val,idx); min2 combine) ----
    #pragma unroll
    for (int off = 1; off <= 2; off <<= 1) {
        #pragma unroll
        for (int m = 0; m < 2; m++)
            #pragma unroll
            for (int lh = 0; lh < 2; lh++) {
                float ov  = __shfl_xor_sync(0xffffffffu, bv[m][lh], off);
                int   oi  = __shfl_xor_sync(0xffffffffu, bi[m][lh], off);
                float ob2 = __shfl_xor_sync(0xffffffffu, b2[m][lh], off);
                b2[m][lh] = fminf(fmaxf(bv[m][lh], ov), fminf(b2[m][lh], ob2));
                if (ov < bv[m][lh] || (ov == bv[m][lh] && oi < bi[m][lh])) {
                    bv[m][lh] = ov; bi[m][lh] = oi;
                }
            }
    }
    // write per-(col-half) row results to smem
    float* sV1 = (float*)(sm + OFF_MV1);
    float* sV2 = (float*)(sm + OFF_MV2);
    int*   sID = (int*)(sm + OFF_MID);
    if (tig == 0) {
        #pragma unroll
        for (int m = 0; m < 2; m++)
            #pragma unroll
            for (int lh = 0; lh < 2; lh++) {
                int row = 32 * rg + 16 * m + g + 8 * lh;
                sV1[ch * 128 + row] = bv[m][lh];
                sV2[ch * 128 + row] = b2[m][lh];
                sID[ch * 128 + row] = bi[m][lh];
            }
    }
    __syncthreads();

    // merge the two col-halves per row; write idx + flag
    if (tid < BM) {
        float v1a = sV1[tid],       v2a = sV2[tid];
        int   ida = sID[tid];
        float v1b = sV1[128 + tid], v2b = sV2[128 + tid];
        int   idb = sID[128 + tid];
        float m1 = v1a; int mi = ida;
        if (v1b < m1 || (v1b == m1 && idb < mi)) { m1 = v1b; mi = idb; }
        float m2 = fminf(fmaxf(v1a, v1b), fminf(v2a, v2b));
        g_idx[r0 + tid] = mi;
        if (m2 - m1 <= FLAG_EPS) {
            int slot = atomicAdd(&g_nflag, 1);
            g_flaglist[slot] = r0 + tid;
        }
    }
}

// ---------------------------------------------------------------------------
// Kernel 2b: exact rescue for ambiguous rows (R5's exact op sequence)
// ---------------------------------------------------------------------------
__global__ void __launch_bounds__(256)
vq_rescue_kernel(const float* __restrict__ lat, const float* __restrict__ emb) {
    __shared__ float sX[8][DIM];
    const int tid  = threadIdx.x;
    const int wid  = tid >> 5;
    const int lane = tid & 31;
    const int nflag = g_nflag;
    const int gwarp = blockIdx.x * 8 + wid;

    for (int item = gwarp; item < nflag; item += 512 * 8) {
        const int row = g_flaglist[item];
        const float4* x4 = (const float4*)(lat + (size_t)row * DIM);
        #pragma unroll
        for (int q = 0; q < 2; q++)
            ((float4*)sX[wid])[lane + 32 * q] = x4[lane + 32 * q];
        __syncwarp();

        const float nx = g_norm_x[row];
        float bv = POS_INF;
        int   bi = 0;
        const int cbase = lane * 32;
        for (int c = 0; c < 32; c++) {
            int code = cbase + c;
            const float4* e4 = (const float4*)(emb + (size_t)code * DIM);
            const float4* xs = (const float4*)sX[wid];
            float master = 0.0f;
            #pragma unroll
            for (int p = 0; p < 8; p++) {
                float acc = 0.0f;
                #pragma unroll
                for (int q = 0; q < 8; q++) {
                    float4 e = e4[p * 8 + q];
                    float4 x = xs[p * 8 + q];
                    acc = __fmaf_rn(x.x, e.x, acc);
                    acc = __fmaf_rn(x.y, e.y, acc);
                    acc = __fmaf_rn(x.z, e.z, acc);
                    acc = __fmaf_rn(x.w, e.w, acc);
                }
                master = __fadd_rn(master, acc);
            }
            float s = __fsub_rn(__fadd_rn(nx, g_norm_e[code]),
                                __fmul_rn(2.0f, master));
            if (s < bv) { bv = s; bi = code; }
        }
        #pragma unroll
        for (int off = 16; off >= 1; off >>= 1) {
            float ov = __shfl_xor_sync(0xffffffffu, bv, off);
            int   oi = __shfl_xor_sync(0xffffffffu, bi, off);
            if (ov < bv || (ov == bv && oi < bi)) { bv = ov; bi = oi; }
        }
        if (lane == 0) g_idx[row] = bi;
        __syncwarp();
    }
}

// ---------------------------------------------------------------------------
// Kernel 2c: epilogue — gather + output + per-block loss (R5 math)
// ---------------------------------------------------------------------------
__global__ void __launch_bounds__(256)
vq_epilogue_kernel(const float* __restrict__ lat, const float* __restrict__ emb,
                   float* __restrict__ out) {
    __shared__ int   sIdx[BM];
    __shared__ float sWS[8];
    const int tid = threadIdx.x;
    const int r0  = blockIdx.x * BM;
    if (tid < BM) sIdx[tid] = g_idx[r0 + tid];
    __syncthreads();

    float lsum = 0.0f;
    const float4* lat4 = (const float4*)lat;
    const float4* emb4 = (const float4*)emb;
    float4*       out4 = (float4*)out;
    for (int t = tid; t < BM * (DIM / 4); t += 256) {
        int row = t >> 6;
        int q   = t & 63;
        int code = sIdx[row];
        float4 e = emb4[(size_t)code * (DIM / 4) + q];
        float4 x = lat4[(size_t)(r0 + row) * (DIM / 4) + q];
        out4[(size_t)(r0 + row) * (DIM / 4) + q] = e;
        float dx = x.x - e.x, dy = x.y - e.y, dz = x.z - e.z, dw = x.w - e.w;
        lsum += dx * dx + dy * dy + dz * dz + dw * dw;
    }
    #pragma unroll
    for (int off = 16; off >= 1; off >>= 1)
        lsum += __shfl_xor_sync(0xffffffffu, lsum, off);
    if ((tid & 31) == 0) sWS[tid >> 5] = lsum;
    __syncthreads();
    if (tid == 0) {
        float tot = 0.0f;
        #pragma unroll
        for (int w = 0; w < 8; w++) tot += sWS[w];
        g_partial[blockIdx.x] = tot;
    }
}

// ---------------------------------------------------------------------------
// Kernel 3: deterministic loss finalize (unchanged)
// ---------------------------------------------------------------------------
__global__ void vq_finalize_kernel(float* __restrict__ out, int out_size) {
    __shared__ float s_warp[16];
    int tid = threadIdx.x;
    float v = g_partial[tid];
    #pragma unroll
    for (int off = 16; off >= 1; off >>= 1)
        v += __shfl_xor_sync(0xffffffffu, v, off);
    if ((tid & 31) == 0) s_warp[tid >> 5] = v;
    __syncthreads();
    if (tid == 0) {
        float tot = 0.0f;
        #pragma unroll
        for (int w = 0; w < 16; w++) tot += s_warp[w];
        float mse = tot / (float)((size_t)N_ROWS * DIM);
        float vq_loss = mse * 1.25f;
        if (out_size > N_ROWS * DIM) out[N_ROWS * DIM] = vq_loss;
    }
}

// ---------------------------------------------------------------------------
extern "C" void kernel_launch(void* const* d_in, const int* in_sizes, int n_in,
                              void* d_out, int out_size) {
    const float* lat = (const float*)d_in[0];
    const float* emb = (const float*)d_in[1];
    float* out = (float*)d_out;

    cudaFuncSetAttribute(vq_main_kernel,
                         cudaFuncAttributeMaxDynamicSharedMemorySize, SMEM_BYTES);

    vq_norms_e_kernel<<<(KCODES + 255) / 256, 256>>>(emb);
    vq_norms_x_kernel<<<(N_ROWS * 32 + 255) / 256, 256>>>(lat);
    vq_convert_e_kernel<<<256, 256>>>(emb);
    vq_main_kernel<<<NBLOCKS, 256, SMEM_BYTES>>>(lat);
    vq_rescue_kernel<<<512, 256>>>(lat, emb);
    vq_epilogue_kernel<<<NBLOCKS, 256>>>(lat, emb, out);
    vq_finalize_kernel<<<1, NBLOCKS>>>(out, out_size);
}

// round 13
// speedup vs baseline: 1.0000x; 1.0000x over previous
#include <cuda_runtime.h>
#include <cuda_bf16.h>
#include <stdint.h>
#include <math.h>

#define N_ROWS 65536
#define DIM    256
#define KCODES 1024
#define BM     128
#define NBLOCKS (N_ROWS / BM)   // 512
#define NCHUNK  8               // codes: 8 chunks of 128
#define NPANEL  4               // K: 4 panels of 64
#define NIDX    (NCHUNK * NPANEL)
#define POS_INF __builtin_huge_valf()
#define FLAG_EPS 8e-5f

// ---------------- device globals ----------------
__device__ float g_norm_e[KCODES];
__device__ float g_norm_x[N_ROWS];
__device__ float g_partial[NBLOCKS];
__device__ int   g_idx[N_ROWS];
__device__ int   g_flaglist[N_ROWS];
__device__ int   g_nflag;
// codebook bf16 limbs, row-major [1024][256]
__device__ __align__(16) __nv_bfloat16 g_eh[KCODES * DIM];
__device__ __align__(16) __nv_bfloat16 g_el[KCODES * DIM];

// ---------------- smem layout (main kernel) ----------------
#define XPITCH 528     // [128 rows][264 bf16] pad -> ldmatrix conflict-free
#define EPITCH 144     // [128 codes][72 bf16]
#define ETILE  (128 * EPITCH)       // 18432 (one limb, one stage)
#define ESTAGE (2 * ETILE)          // 36864 (EH + EL, one stage)
#define OFF_XH  0                   // 67584
#define OFF_XL  67584               // 67584 (end 135168)
#define OFF_E   135168              // 2 stages x (EH,EL) = 73728 (end 208896)
#define OFF_NE  208896              // 4096
#define OFF_NX  212992              // 512
#define OFF_MV1 213504              // float [2][128]  (min1 per col-half)
#define OFF_MV2 214528              // float [2][128]  (min2)
#define OFF_MID 215552              // int   [2][128]  (idx)
#define SMEM_BYTES 216576

__device__ __forceinline__ uint32_t smem_u32(const void* p) {
    uint32_t a;
    asm("{ .reg .u64 t; cvta.to.shared.u64 t, %1; cvt.u32.u64 %0, t; }" : "=r"(a) : "l"(p));
    return a;
}
__device__ __forceinline__ void ldm_x4(uint32_t& r0, uint32_t& r1, uint32_t& r2, uint32_t& r3,
                                       uint32_t addr) {
    asm volatile("ldmatrix.sync.aligned.m8n8.x4.shared.b16 {%0,%1,%2,%3}, [%4];"
                 : "=r"(r0), "=r"(r1), "=r"(r2), "=r"(r3) : "r"(addr));
}
__device__ __forceinline__ void mma16816(float* c, uint32_t a0, uint32_t a1, uint32_t a2,
                                         uint32_t a3, uint32_t b0, uint32_t b1) {
    asm volatile("mma.sync.aligned.m16n8k16.row.col.f32.bf16.bf16.f32 "
                 "{%0,%1,%2,%3}, {%4,%5,%6,%7}, {%8,%9}, {%0,%1,%2,%3};"
                 : "+f"(c[0]), "+f"(c[1]), "+f"(c[2]), "+f"(c[3])
                 : "r"(a0), "r"(a1), "r"(a2), "r"(a3), "r"(b0), "r"(b1));
}
__device__ __forceinline__ void cp_async16(uint32_t dst, const void* src) {
    size_t g = __cvta_generic_to_global(src);
    asm volatile("cp.async.cg.shared.global [%0], [%1], 16;" :: "r"(dst), "l"(g) : "memory");
}
#define CP_COMMIT() asm volatile("cp.async.commit_group;" ::: "memory")
template <int N>
__device__ __forceinline__ void cp_wait() {
    asm volatile("cp.async.wait_group %0;" :: "n"(N) : "memory");
}
__device__ __forceinline__ uint32_t pack2(__nv_bfloat16 a, __nv_bfloat16 b) {
    __nv_bfloat162 p = __halves2bfloat162(a, b);
    return reinterpret_cast<uint32_t&>(p);
}
__device__ __forceinline__ void split2(float x, __nv_bfloat16& h, __nv_bfloat16& l) {
    h = __float2bfloat16(x);
    l = __float2bfloat16(__fsub_rn(x, __bfloat162float(h)));
}

// ---------------------------------------------------------------------------
// Kernel 1a: ||e_k||^2 + flag-counter reset
// ---------------------------------------------------------------------------
__global__ void vq_norms_e_kernel(const float* __restrict__ emb) {
    if (blockIdx.x == 0 && threadIdx.x == 0) g_nflag = 0;
    int k = blockIdx.x * blockDim.x + threadIdx.x;
    if (k < KCODES) {
        const float4* e4 = (const float4*)(emb + (size_t)k * DIM);
        float s = 0.0f;
        #pragma unroll 8
        for (int q = 0; q < DIM / 4; q++) {
            float4 v = e4[q];
            s += v.x * v.x + v.y * v.y + v.z * v.z + v.w * v.w;
        }
        g_norm_e[k] = s;
    }
}
// ---------------------------------------------------------------------------
// Kernel 1b: ||x_r||^2  (bit-identical to passing version)
// ---------------------------------------------------------------------------
__global__ void vq_norms_x_kernel(const float* __restrict__ lat) {
    int warp = (blockIdx.x * blockDim.x + threadIdx.x) >> 5;
    int lane = threadIdx.x & 31;
    if (warp < N_ROWS) {
        const float4* x4 = (const float4*)(lat + (size_t)warp * DIM);
        float s = 0.0f;
        #pragma unroll
        for (int q = 0; q < 2; q++) {
            float4 v = x4[lane + 32 * q];
            s += v.x * v.x + v.y * v.y + v.z * v.z + v.w * v.w;
        }
        #pragma unroll
        for (int off = 16; off >= 1; off >>= 1)
            s += __shfl_xor_sync(0xffffffffu, s, off);
        if (lane == 0) g_norm_x[warp] = s;
    }
}
// ---------------------------------------------------------------------------
// Kernel 1c: codebook -> bf16 limbs, row-major
// ---------------------------------------------------------------------------
__global__ void vq_convert_e_kernel(const float* __restrict__ emb) {
    int t = blockIdx.x * blockDim.x + threadIdx.x;   // 65536
    int k  = t >> 6;
    int c4 = t & 63;
    float4 v = ((const float4*)emb)[(size_t)k * 64 + c4];
    __nv_bfloat16 h0, h1, h2, h3, l0, l1, l2, l3;
    split2(v.x, h0, l0); split2(v.y, h1, l1);
    split2(v.z, h2, l2); split2(v.w, h3, l3);
    uint2 uh; uh.x = pack2(h0, h1); uh.y = pack2(h2, h3);
    uint2 ul; ul.x = pack2(l0, l1); ul.y = pack2(l2, l3);
    *(uint2*)((char*)g_eh + (size_t)k * 512 + c4 * 8) = uh;
    *(uint2*)((char*)g_el + (size_t)k * 512 + c4 * 8) = ul;
}

// ---------------------------------------------------------------------------
// Kernel 2: mma.sync split-bf16 GEMM (32x64 warp tiles, cp.async pipelined,
//           limb passes software-pipelined across accumulators)
//           + argmin(min1,min2) + ambiguity flag
// ---------------------------------------------------------------------------
__global__ void __launch_bounds__(256, 1)
vq_main_kernel(const float* __restrict__ lat) {
    extern __shared__ char sm[];
    const uint32_t sb = smem_u32(sm);

    const int tid  = threadIdx.x;
    const int wid  = tid >> 5;
    const int lane = tid & 31;
    const int g    = lane >> 2;
    const int tig  = lane & 3;
    const int rg   = wid & 3;        // row group: rows [32*rg, 32*rg+32)
    const int ch   = wid >> 2;       // col half:  cols [64*ch, 64*ch+64)
    const int r0   = blockIdx.x * BM;

    float* sNE = (float*)(sm + OFF_NE);
    float* sNX = (float*)(sm + OFF_NX);

    // ---- prologue: issue first E panel immediately ----
    {
        const char* srcH = (const char*)g_eh;           // cc=0, p=0
        const char* srcL = (const char*)g_el;
        #pragma unroll
        for (int t = tid; t < 1024; t += 256) {
            int r = t >> 3, c16 = t & 7;
            cp_async16(sb + OFF_E + r * EPITCH + c16 * 16, srcH + (size_t)r * 512 + c16 * 16);
            cp_async16(sb + OFF_E + ETILE + r * EPITCH + c16 * 16, srcL + (size_t)r * 512 + c16 * 16);
        }
        CP_COMMIT();
    }

    for (int t = tid; t < KCODES; t += 256) sNE[t] = g_norm_e[t];
    if (tid < BM) sNX[tid] = g_norm_x[r0 + tid];

    // build x limb tiles (x read once for the GEMM)
    const float4* lat4 = (const float4*)lat;
    for (int t = tid; t < BM * 64; t += 256) {
        int row = t >> 6, c4 = t & 63;
        float4 v = lat4[(size_t)(r0 + row) * 64 + c4];
        __nv_bfloat16 h0, h1, h2, h3, l0, l1, l2, l3;
        split2(v.x, h0, l0); split2(v.y, h1, l1);
        split2(v.z, h2, l2); split2(v.w, h3, l3);
        uint2 uh; uh.x = pack2(h0, h1); uh.y = pack2(h2, h3);
        uint2 ul; ul.x = pack2(l0, l1); ul.y = pack2(l2, l3);
        *(uint2*)(sm + OFF_XH + row * XPITCH + c4 * 8) = uh;
        *(uint2*)(sm + OFF_XL + row * XPITCH + c4 * 8) = ul;
    }
    __syncthreads();

    // ldmatrix lane addressing
    const uint32_t a_off0 = (uint32_t)(32 * rg + (lane & 15)) * XPITCH + (lane >> 4) * 16;
    const uint32_t a_off1 = a_off0 + 16 * XPITCH;
    const uint32_t b_lane = (uint32_t)((lane & 7) + ((lane >> 4) & 1) * 8) * EPITCH
                          + ((lane >> 3) & 1) * 16
                          + (uint32_t)(64 * ch) * EPITCH;

    const float nx00 = sNX[32 * rg + g];           // m=0 lo
    const float nx01 = sNX[32 * rg + g + 8];       // m=0 hi
    const float nx10 = sNX[32 * rg + 16 + g];      // m=1 lo
    const float nx11 = sNX[32 * rg + 16 + g + 8];  // m=1 hi

    float bv[2][2], b2[2][2];
    int   bi[2][2];
    #pragma unroll
    for (int m = 0; m < 2; m++)
        #pragma unroll
        for (int lh = 0; lh < 2; lh++) {
            bv[m][lh] = POS_INF; b2[m][lh] = POS_INF; bi[m][lh] = 0;
        }

    float acc[2][8][4];

    for (int idx = 0; idx < NIDX; idx++) {
        const int cc  = idx >> 2;
        const int p   = idx & 3;
        const int cur = idx & 1;

        // issue next panel into alternate stage, then wait for current
        if (idx + 1 < NIDX) {
            const int ncc = (idx + 1) >> 2, np2 = (idx + 1) & 3, nst = (idx + 1) & 1;
            const char* srcH = (const char*)g_eh + ((size_t)ncc * 128) * 512 + np2 * 128;
            const char* srcL = (const char*)g_el + ((size_t)ncc * 128) * 512 + np2 * 128;
            const uint32_t dH = sb + OFF_E + nst * ESTAGE;
            const uint32_t dL = dH + ETILE;
            #pragma unroll
            for (int t = tid; t < 1024; t += 256) {
                int r = t >> 3, c16 = t & 7;
                cp_async16(dH + r * EPITCH + c16 * 16, srcH + (size_t)r * 512 + c16 * 16);
                cp_async16(dL + r * EPITCH + c16 * 16, srcL + (size_t)r * 512 + c16 * 16);
            }
            CP_COMMIT();
            cp_wait<1>();
        } else {
            cp_wait<0>();
        }
        __syncthreads();

        if (p == 0) {
            #pragma unroll
            for (int m = 0; m < 2; m++)
                #pragma unroll
                for (int j = 0; j < 8; j++)
                    #pragma unroll
                    for (int q = 0; q < 4; q++) acc[m][j][q] = 0.0f;
        }

        const uint32_t bh_base = sb + OFF_E + cur * ESTAGE + b_lane;
        const uint32_t bl_base = bh_base + ETILE;

        #pragma unroll
        for (int kk = 0; kk < 4; kk++) {
            const int ks = p * 4 + kk;
            uint32_t ah[2][4], al[2][4];
            ldm_x4(ah[0][0], ah[0][1], ah[0][2], ah[0][3], sb + OFF_XH + a_off0 + ks * 32);
            ldm_x4(al[0][0], al[0][1], al[0][2], al[0][3], sb + OFF_XL + a_off0 + ks * 32);
            ldm_x4(ah[1][0], ah[1][1], ah[1][2], ah[1][3], sb + OFF_XH + a_off1 + ks * 32);
            ldm_x4(al[1][0], al[1][1], al[1][2], al[1][3], sb + OFF_XL + a_off1 + ks * 32);
            uint32_t bh[4][4], bl[4][4];
            #pragma unroll
            for (int nt = 0; nt < 4; nt++) {
                ldm_x4(bh[nt][0], bh[nt][1], bh[nt][2], bh[nt][3],
                       bh_base + nt * (16 * EPITCH) + kk * 32);
                ldm_x4(bl[nt][0], bl[nt][1], bl[nt][2], bl[nt][3],
                       bl_base + nt * (16 * EPITCH) + kk * 32);
            }
            // pass 1: hh  (16 independent MMAs)
            #pragma unroll
            for (int m = 0; m < 2; m++)
                #pragma unroll
                for (int nt = 0; nt < 4; nt++) {
                    mma16816(acc[m][2 * nt],     ah[m][0], ah[m][1], ah[m][2], ah[m][3],
                             bh[nt][0], bh[nt][1]);
                    mma16816(acc[m][2 * nt + 1], ah[m][0], ah[m][1], ah[m][2], ah[m][3],
                             bh[nt][2], bh[nt][3]);
                }
            // pass 2: lh  (each 16 instructions after its hh)
            #pragma unroll
            for (int m = 0; m < 2; m++)
                #pragma unroll
                for (int nt = 0; nt < 4; nt++) {
                    mma16816(acc[m][2 * nt],     al[m][0], al[m][1], al[m][2], al[m][3],
                             bh[nt][0], bh[nt][1]);
                    mma16816(acc[m][2 * nt + 1], al[m][0], al[m][1], al[m][2], al[m][3],
                             bh[nt][2], bh[nt][3]);
                }
            // pass 3: hl
            #pragma unroll
            for (int m = 0; m < 2; m++)
                #pragma unroll
                for (int nt = 0; nt < 4; nt++) {
                    mma16816(acc[m][2 * nt],     ah[m][0], ah[m][1], ah[m][2], ah[m][3],
                             bl[nt][0], bl[nt][1]);
                    mma16816(acc[m][2 * nt + 1], ah[m][0], ah[m][1], ah[m][2], ah[m][3],
                             bl[nt][2], bl[nt][3]);
                }
        }
        __syncthreads();   // all warps done with stage `cur` before it is refilled

        // ---- per-chunk argmin fold (after panel 3) ----
        if (p == 3) {
            const float* nep = sNE + cc * 128;
            #pragma unroll
            for (int j = 0; j < 8; j++) {
                const int nt = j >> 1, h = j & 1;
                const int nc = 64 * ch + nt * 16 + 8 * h + 2 * tig;
                const int col0 = cc * 128 + nc;
                const float ne0 = nep[nc], ne1 = nep[nc + 1];
                float s;
                #pragma unroll
                for (int m = 0; m < 2; m++) {
                    const float nxl = (m == 0) ? nx00 : nx10;
                    const float nxh = (m == 0) ? nx01 : nx11;
                    s = __fsub_rn(__fadd_rn(nxl, ne0), __fmul_rn(2.0f, acc[m][j][0]));
                    if (s < bv[m][0]) { b2[m][0] = bv[m][0]; bv[m][0] = s; bi[m][0] = col0; }
                    else if (s < b2[m][0]) b2[m][0] = s;
                    s = __fsub_rn(__fadd_rn(nxl, ne1), __fmul_rn(2.0f, acc[m][j][1]));
                    if (s < bv[m][0]) { b2[m][0] = bv[m][0]; bv[m][0] = s; bi[m][0] = col0 + 1; }
                    else if (s < b2[m][0]) b2[m][0] = s;
                    s = __fsub_rn(__fadd_rn(nxh, ne0), __fmul_rn(2.0f, acc[m][j][2]));
                    if (s < bv[m][1]) { b2[m][1] = bv[m][1]; bv[m][1] = s; bi[m][1] = col0; }
                    else if (s < b2[m][1]) b2[m][1] = s;
                    s = __fsub_rn(__fadd_rn(nxh, ne1), __fmul_rn(2.0f, acc[m][j][3]));
                    if (s < bv[m][1]) { b2[m][1] = bv[m][1]; bv[m][1] = s; bi[m][1] = col0 + 1; }
                    else if (s < b2[m][1]) b2[m][1] = s;
                }
            }
        }
    }

    // ---- quad reduce (lex (val,idx); min2 combine) ----
    #pragma unroll
    for (int off = 1; off <= 2; off <<= 1) {
        #pragma unroll
        for (int m = 0; m < 2; m++)
            #pragma unroll
            for (int lh = 0; lh < 2; lh++) {
                float ov  = __shfl_xor_sync(0xffffffffu, bv[m][lh], off);
                int   oi  = __shfl_xor_sync(0xffffffffu, bi[m][lh], off);
                float ob2 = __shfl_xor_sync(0xffffffffu, b2[m][lh], off);
                b2[m][lh] = fminf(fmaxf(bv[m][lh], ov), fminf(b2[m][lh], ob2));
                if (ov < bv[m][lh] || (ov == bv[m][lh] && oi < bi[m][lh])) {
                    bv[m][lh] = ov; bi[m][lh] = oi;
                }
            }
    }
    // write per-(col-half) row results to smem
    float* sV1 = (float*)(sm + OFF_MV1);
    float* sV2 = (float*)(sm + OFF_MV2);
    int*   sID = (int*)(sm + OFF_MID);
    if (tig == 0) {
        #pragma unroll
        for (int m = 0; m < 2; m++)
            #pragma unroll
            for (int lh = 0; lh < 2; lh++) {
                int row = 32 * rg + 16 * m + g + 8 * lh;
                sV1[ch * 128 + row] = bv[m][lh];
                sV2[ch * 128 + row] = b2[m][lh];
                sID[ch * 128 + row] = bi[m][lh];
            }
    }
    __syncthreads();

    // merge the two col-halves per row; write idx + flag
    if (tid < BM) {
        float v1a = sV1[tid],       v2a = sV2[tid];
        int   ida = sID[tid];
        float v1b = sV1[128 + tid], v2b = sV2[128 + tid];
        int   idb = sID[128 + tid];
        float m1 = v1a; int mi = ida;
        if (v1b < m1 || (v1b == m1 && idb < mi)) { m1 = v1b; mi = idb; }
        float m2 = fminf(fmaxf(v1a, v1b), fminf(v2a, v2b));
        g_idx[r0 + tid] = mi;
        if (m2 - m1 <= FLAG_EPS) {
            int slot = atomicAdd(&g_nflag, 1);
            g_flaglist[slot] = r0 + tid;
        }
    }
}

// ---------------------------------------------------------------------------
// Kernel 2b: exact rescue for ambiguous rows (R5's exact op sequence)
// ---------------------------------------------------------------------------
__global__ void __launch_bounds__(256)
vq_rescue_kernel(const float* __restrict__ lat, const float* __restrict__ emb) {
    __shared__ float sX[8][DIM];
    const int tid  = threadIdx.x;
    const int wid  = tid >> 5;
    const int lane = tid & 31;
    const int nflag = g_nflag;
    const int gwarp = blockIdx.x * 8 + wid;

    for (int item = gwarp; item < nflag; item += 512 * 8) {
        const int row = g_flaglist[item];
        const float4* x4 = (const float4*)(lat + (size_t)row * DIM);
        #pragma unroll
        for (int q = 0; q < 2; q++)
            ((float4*)sX[wid])[lane + 32 * q] = x4[lane + 32 * q];
        __syncwarp();

        const float nx = g_norm_x[row];
        float bv = POS_INF;
        int   bi = 0;
        const int cbase = lane * 32;
        for (int c = 0; c < 32; c++) {
            int code = cbase + c;
            const float4* e4 = (const float4*)(emb + (size_t)code * DIM);
            const float4* xs = (const float4*)sX[wid];
            float master = 0.0f;
            #pragma unroll
            for (int p = 0; p < 8; p++) {
                float acc = 0.0f;
                #pragma unroll
                for (int q = 0; q < 8; q++) {
                    float4 e = e4[p * 8 + q];
                    float4 x = xs[p * 8 + q];
                    acc = __fmaf_rn(x.x, e.x, acc);
                    acc = __fmaf_rn(x.y, e.y, acc);
                    acc = __fmaf_rn(x.z, e.z, acc);
                    acc = __fmaf_rn(x.w, e.w, acc);
                }
                master = __fadd_rn(master, acc);
            }
            float s = __fsub_rn(__fadd_rn(nx, g_norm_e[code]),
                                __fmul_rn(2.0f, master));
            if (s < bv) { bv = s; bi = code; }
        }
        #pragma unroll
        for (int off = 16; off >= 1; off >>= 1) {
            float ov = __shfl_xor_sync(0xffffffffu, bv, off);
            int   oi = __shfl_xor_sync(0xffffffffu, bi, off);
            if (ov < bv || (ov == bv && oi < bi)) { bv = ov; bi = oi; }
        }
        if (lane == 0) g_idx[row] = bi;
        __syncwarp();
    }
}

// ---------------------------------------------------------------------------
// Kernel 2c: epilogue — gather + output + per-block loss (R5 math)
// ---------------------------------------------------------------------------
__global__ void __launch_bounds__(256)
vq_epilogue_kernel(const float* __restrict__ lat, const float* __restrict__ emb,
                   float* __restrict__ out) {
    __shared__ int   sIdx[BM];
    __shared__ float sWS[8];
    const int tid = threadIdx.x;
    const int r0  = blockIdx.x * BM;
    if (tid < BM) sIdx[tid] = g_idx[r0 + tid];
    __syncthreads();

    float lsum = 0.0f;
    const float4* lat4 = (const float4*)lat;
    const float4* emb4 = (const float4*)emb;
    float4*       out4 = (float4*)out;
    for (int t = tid; t < BM * (DIM / 4); t += 256) {
        int row = t >> 6;
        int q   = t & 63;
        int code = sIdx[row];
        float4 e = emb4[(size_t)code * (DIM / 4) + q];
        float4 x = lat4[(size_t)(r0 + row) * (DIM / 4) + q];
        out4[(size_t)(r0 + row) * (DIM / 4) + q] = e;
        float dx = x.x - e.x, dy = x.y - e.y, dz = x.z - e.z, dw = x.w - e.w;
        lsum += dx * dx + dy * dy + dz * dz + dw * dw;
    }
    #pragma unroll
    for (int off = 16; off >= 1; off >>= 1)
        lsum += __shfl_xor_sync(0xffffffffu, lsum, off);
    if ((tid & 31) == 0) sWS[tid >> 5] = lsum;
    __syncthreads();
    if (tid == 0) {
        float tot = 0.0f;
        #pragma unroll
        for (int w = 0; w < 8; w++) tot += sWS[w];
        g_partial[blockIdx.x] = tot;
    }
}

// ---------------------------------------------------------------------------
// Kernel 3: deterministic loss finalize (unchanged)
// ---------------------------------------------------------------------------
__global__ void vq_finalize_kernel(float* __restrict__ out, int out_size) {
    __shared__ float s_warp[16];
    int tid = threadIdx.x;
    float v = g_partial[tid];
    #pragma unroll
    for (int off = 16; off >= 1; off >>= 1)
        v += __shfl_xor_sync(0xffffffffu, v, off);
    if ((tid & 31) == 0) s_warp[tid >> 5] = v;
    __syncthreads();
    if (tid == 0) {
        float tot = 0.0f;
        #pragma unroll
        for (int w = 0; w < 16; w++) tot += s_warp[w];
        float mse = tot / (float)((size_t)N_ROWS * DIM);
        float vq_loss = mse * 1.25f;
        if (out_size > N_ROWS * DIM) out[N_ROWS * DIM] = vq_loss;
    }
}

// ---------------------------------------------------------------------------
extern "C" void kernel_launch(void* const* d_in, const int* in_sizes, int n_in,
                              void* d_out, int out_size) {
    const float* lat = (const float*)d_in[0];
    const float* emb = (const float*)d_in[1];
    float* out = (float*)d_out;

    cudaFuncSetAttribute(vq_main_kernel,
                         cudaFuncAttributeMaxDynamicSharedMemorySize, SMEM_BYTES);

    vq_norms_e_kernel<<<(KCODES + 255) / 256, 256>>>(emb);
    vq_norms_x_kernel<<<(N_ROWS * 32 + 255) / 256, 256>>>(lat);
    vq_convert_e_kernel<<<256, 256>>>(emb);
    vq_main_kernel<<<NBLOCKS, 256, SMEM_BYTES>>>(lat);
    vq_rescue_kernel<<<512, 256>>>(lat, emb);
    vq_epilogue_kernel<<<NBLOCKS, 256>>>(lat, emb, out);
    vq_finalize_kernel<<<1, NBLOCKS>>>(out, out_size);
}